// round 1
// baseline (speedup 1.0000x reference)
#include <cuda_runtime.h>
#include <cuda_bf16.h>

#define FULLMASK 0xFFFFFFFFu
constexpr int G = 4;           // samples per CTA
constexpr int NWARP = 8;       // warps per CTA

// In-warp 128-point unnormalized Walsh-Hadamard transform.
// Layout: lane l holds u[q] = vec[q*32 + l], q = 0..3.
// Stages commute, so do the two register-level strides (64, 32) first,
// then lane-level strides 16..1 via shfl_xor. Butterfly: lower index gets
// a+b, upper gets a-b  ==  u_new = fma(sign, u, partner).
__device__ __forceinline__ void fwht128(float &u0, float &u1, float &u2, float &u3, int lane) {
    float t0 = u0 + u2, t2 = u0 - u2;
    float t1 = u1 + u3, t3 = u1 - u3;
    u0 = t0 + t1; u1 = t0 - t1;
    u2 = t2 + t3; u3 = t2 - t3;
#pragma unroll
    for (int m = 16; m >= 1; m >>= 1) {
        float s = (lane & m) ? -1.0f : 1.0f;
        float p0 = __shfl_xor_sync(FULLMASK, u0, m);
        float p1 = __shfl_xor_sync(FULLMASK, u1, m);
        float p2 = __shfl_xor_sync(FULLMASK, u2, m);
        float p3 = __shfl_xor_sync(FULLMASK, u3, m);
        u0 = fmaf(s, u0, p0);
        u1 = fmaf(s, u1, p1);
        u2 = fmaf(s, u2, p2);
        u3 = fmaf(s, u3, p3);
    }
}

__device__ __forceinline__ float warp_sum(float v) {
#pragma unroll
    for (int m = 16; m >= 1; m >>= 1) v += __shfl_xor_sync(FULLMASK, v, m);
    return v;
}

struct FF {
    float fb[4], fg[4], fs[4];
    int   fp[4];
};

__device__ __forceinline__ void ff_load(FF &f, int r, int lane,
                                        const float* __restrict__ ffB,
                                        const float* __restrict__ ffG,
                                        const float* __restrict__ ffS,
                                        const int*   __restrict__ ffP) {
    int o = r * 128 + lane;
#pragma unroll
    for (int q = 0; q < 4; q++) {
        f.fb[q] = ffB[o + 32 * q];
        f.fg[q] = ffG[o + 32 * q];
        f.fs[q] = ffS[o + 32 * q] * (1.0f / 128.0f);  // fold /Z_DIM
        f.fp[q] = ffP[o + 32 * q];
    }
}

// v = ffS/128 * H( ffG * P( H( ffB * z ) ) )   for one sample's z (in smem)
__device__ __forceinline__ void ff_apply(const FF &f, const float* __restrict__ zg,
                                         float* __restrict__ stg, int lane, float u[4]) {
#pragma unroll
    for (int q = 0; q < 4; q++) u[q] = f.fb[q] * zg[q * 32 + lane];
    fwht128(u[0], u[1], u[2], u[3], lane);
    __syncwarp();  // protect previous iteration's staging reads
#pragma unroll
    for (int q = 0; q < 4; q++) stg[q * 32 + lane] = u[q];
    __syncwarp();
#pragma unroll
    for (int q = 0; q < 4; q++) u[q] = stg[f.fp[q]] * f.fg[q];
    fwht128(u[0], u[1], u[2], u[3], lane);
#pragma unroll
    for (int q = 0; q < 4; q++) u[q] *= f.fs[q];
}

__global__ __launch_bounds__(256, 4)
void mlp_fastfood_kernel(const float* __restrict__ x,   // (2048, 32)
                         const float* __restrict__ z,   // (2048, 128)
                         const float* __restrict__ W0,  // (128, 32)
                         const float* __restrict__ b0,  // (128)
                         const float* __restrict__ W1,  // (128, 128)
                         const float* __restrict__ b1,  // (128)
                         const float* __restrict__ W2,  // (16, 128)
                         const float* __restrict__ b2,  // (16)
                         const float* __restrict__ ffB, // (179, 128)
                         const float* __restrict__ ffG,
                         const float* __restrict__ ffS,
                         const int*   __restrict__ ffP,
                         float* __restrict__ out)       // (2048, 16)
{
    __shared__ float sh_z[G][128];
    __shared__ float sh_x[G][32];
    __shared__ float sh_h1[G][128];
    __shared__ float sh_h2[G][128];
    __shared__ float sh_bd0[G][128];
    __shared__ float sh_bd1[G][128];
    __shared__ float sh_bd2[G][128];
    __shared__ float sh_stage[NWARP][128];

    const int tid  = threadIdx.x;
    const int warp = tid >> 5;
    const int lane = tid & 31;
    const int base = blockIdx.x * G;

    // Load z and x for this CTA's G samples
    for (int k = tid; k < G * 128; k += 256) {
        int g = k >> 7, i = k & 127;
        sh_z[g][i] = z[(base + g) * 128 + i];
    }
    for (int k = tid; k < G * 32; k += 256) {
        int g = k >> 5, i = k & 31;
        sh_x[g][i] = x[(base + g) * 32 + i];
    }
    __syncthreads();

    float* stg = sh_stage[warp];

    // ---------------- Phase A: layer-0 weight blocks (0..31) + bias blocks (32,161,178)
    for (int t = warp; t < 35; t += NWARP) {
        FF f; float u[4];
        if (t < 32) {
            // block t covers W0 rows 4t..4t+3 (each 32 wide)
            ff_load(f, t, lane, ffB, ffG, ffS, ffP);
            float w[4];
#pragma unroll
            for (int q = 0; q < 4; q++) w[q] = W0[(4 * t + q) * 32 + lane];
#pragma unroll 1
            for (int g = 0; g < G; g++) {
                ff_apply(f, sh_z[g], stg, lane, u);
                float xv = sh_x[g][lane];
#pragma unroll
                for (int q = 0; q < 4; q++) {
                    float s = warp_sum((w[q] + u[q]) * xv);
                    if (lane == 0) sh_h1[g][4 * t + q] = s;
                }
            }
        } else {
            // bias delta blocks: depend only on z, compute all here
            int r = (t == 32) ? 32 : (t == 33) ? 161 : 178;
            float (*bd)[128] = (t == 32) ? sh_bd0 : (t == 33) ? sh_bd1 : sh_bd2;
            ff_load(f, r, lane, ffB, ffG, ffS, ffP);
#pragma unroll 1
            for (int g = 0; g < G; g++) {
                ff_apply(f, sh_z[g], stg, lane, u);
#pragma unroll
                for (int q = 0; q < 4; q++) bd[g][q * 32 + lane] = u[q];
            }
        }
    }
    __syncthreads();
    // h1 = relu(acc + b0 + bd0)
    for (int k = tid; k < G * 128; k += 256) {
        int g = k >> 7, j = k & 127;
        sh_h1[g][j] = fmaxf(sh_h1[g][j] + b0[j] + sh_bd0[g][j], 0.0f);
    }
    __syncthreads();

    // ---------------- Phase B: layer-1 weight blocks (33..160), block t = W1 row t
    for (int t = warp; t < 128; t += NWARP) {
        FF f; float u[4];
        ff_load(f, 33 + t, lane, ffB, ffG, ffS, ffP);
        float w[4];
#pragma unroll
        for (int q = 0; q < 4; q++) w[q] = W1[t * 128 + q * 32 + lane];
#pragma unroll 1
        for (int g = 0; g < G; g++) {
            ff_apply(f, sh_z[g], stg, lane, u);
            float acc = 0.0f;
#pragma unroll
            for (int q = 0; q < 4; q++) acc += (w[q] + u[q]) * sh_h1[g][q * 32 + lane];
            acc = warp_sum(acc);
            if (lane == 0) sh_h2[g][t] = acc;
        }
    }
    __syncthreads();
    // h2 = relu(acc + b1 + bd1)
    for (int k = tid; k < G * 128; k += 256) {
        int g = k >> 7, j = k & 127;
        sh_h2[g][j] = fmaxf(sh_h2[g][j] + b1[j] + sh_bd1[g][j], 0.0f);
    }
    __syncthreads();

    // ---------------- Phase C: layer-2 weight blocks (162..177), block t = W2 row t
    for (int t = warp; t < 16; t += NWARP) {
        FF f; float u[4];
        ff_load(f, 162 + t, lane, ffB, ffG, ffS, ffP);
        float w[4];
#pragma unroll
        for (int q = 0; q < 4; q++) w[q] = W2[t * 128 + q * 32 + lane];
        float bias = b2[t];
#pragma unroll 1
        for (int g = 0; g < G; g++) {
            ff_apply(f, sh_z[g], stg, lane, u);
            float acc = 0.0f;
#pragma unroll
            for (int q = 0; q < 4; q++) acc += (w[q] + u[q]) * sh_h2[g][q * 32 + lane];
            acc = warp_sum(acc);
            if (lane == 0) out[(base + g) * 16 + t] = acc + bias + sh_bd2[g][t];
        }
    }
}

extern "C" void kernel_launch(void* const* d_in, const int* in_sizes, int n_in,
                              void* d_out, int out_size) {
    (void)in_sizes; (void)n_in; (void)out_size;
    const float* x   = (const float*)d_in[0];
    const float* z   = (const float*)d_in[1];
    const float* W0  = (const float*)d_in[2];
    const float* b0  = (const float*)d_in[3];
    const float* W1  = (const float*)d_in[4];
    const float* b1  = (const float*)d_in[5];
    const float* W2  = (const float*)d_in[6];
    const float* b2  = (const float*)d_in[7];
    const float* ffB = (const float*)d_in[8];
    const float* ffG = (const float*)d_in[9];
    const float* ffS = (const float*)d_in[10];
    const int*   ffP = (const int*)d_in[11];
    float* out = (float*)d_out;

    // 2048 samples / G=4 per CTA = 512 CTAs
    mlp_fastfood_kernel<<<512, 256>>>(x, z, W0, b0, W1, b1, W2, b2,
                                      ffB, ffG, ffS, ffP, out);
}

// round 2
// speedup vs baseline: 1.0713x; 1.0713x over previous
#include <cuda_runtime.h>
#include <cuda_bf16.h>

#define FULLMASK 0xFFFFFFFFu
constexpr int G = 4;           // samples per CTA
constexpr int NWARP = 8;       // warps per CTA

// In-warp 128-point unnormalized WHT, CONTIGUOUS layout:
// lane l holds u[q] = vec[4*l + q], q = 0..3.
// Stages commute: do strides 1,2 in registers, strides 4..64 via shfl_xor
// with lane masks m = 1,2,4,8,16 (sign from lane&m).
__device__ __forceinline__ void fwht128c(float &u0, float &u1, float &u2, float &u3, int lane) {
    // stride 1
    float a0 = u0 + u1, a1 = u0 - u1;
    float a2 = u2 + u3, a3 = u2 - u3;
    // stride 2
    u0 = a0 + a2; u2 = a0 - a2;
    u1 = a1 + a3; u3 = a1 - a3;
#pragma unroll
    for (int m = 1; m <= 16; m <<= 1) {
        float s = (lane & m) ? -1.0f : 1.0f;
        float p0 = __shfl_xor_sync(FULLMASK, u0, m);
        float p1 = __shfl_xor_sync(FULLMASK, u1, m);
        float p2 = __shfl_xor_sync(FULLMASK, u2, m);
        float p3 = __shfl_xor_sync(FULLMASK, u3, m);
        u0 = fmaf(s, u0, p0);
        u1 = fmaf(s, u1, p1);
        u2 = fmaf(s, u2, p2);
        u3 = fmaf(s, u3, p3);
    }
}

struct FF {
    float4 fb, fg, fs;
    int4   fp;
};

__device__ __forceinline__ void ff_load(FF &f, int r, int lane,
                                        const float* __restrict__ ffB,
                                        const float* __restrict__ ffG,
                                        const float* __restrict__ ffS,
                                        const int*   __restrict__ ffP) {
    f.fb = reinterpret_cast<const float4*>(ffB + r * 128)[lane];
    f.fg = reinterpret_cast<const float4*>(ffG + r * 128)[lane];
    float4 s = reinterpret_cast<const float4*>(ffS + r * 128)[lane];
    f.fs = make_float4(s.x * (1.0f/128.0f), s.y * (1.0f/128.0f),
                       s.z * (1.0f/128.0f), s.w * (1.0f/128.0f));
    f.fp = reinterpret_cast<const int4*>(ffP + r * 128)[lane];
}

// v = ffS/128 * H( ffG * P( H( ffB * z ) ) ); z in smem (contiguous), result
// in u[0..3] = v[4*lane + q]. stg: 128-float staging buffer (per warp, per parity).
__device__ __forceinline__ void ff_apply(const FF &f, const float* __restrict__ zg,
                                         float* __restrict__ stg, int lane,
                                         float &u0, float &u1, float &u2, float &u3) {
    float4 z4 = reinterpret_cast<const float4*>(zg)[lane];
    u0 = f.fb.x * z4.x; u1 = f.fb.y * z4.y;
    u2 = f.fb.z * z4.z; u3 = f.fb.w * z4.w;
    fwht128c(u0, u1, u2, u3, lane);
    reinterpret_cast<float4*>(stg)[lane] = make_float4(u0, u1, u2, u3);
    __syncwarp();
    u0 = stg[f.fp.x] * f.fg.x;
    u1 = stg[f.fp.y] * f.fg.y;
    u2 = stg[f.fp.z] * f.fg.z;
    u3 = stg[f.fp.w] * f.fg.w;
    fwht128c(u0, u1, u2, u3, lane);
    u0 *= f.fs.x; u1 *= f.fs.y; u2 *= f.fs.z; u3 *= f.fs.w;
}

__global__ __launch_bounds__(256, 4)
void mlp_fastfood_kernel(const float* __restrict__ x,   // (2048, 32)
                         const float* __restrict__ z,   // (2048, 128)
                         const float* __restrict__ W0,  // (128, 32)
                         const float* __restrict__ b0,  // (128)
                         const float* __restrict__ W1,  // (128, 128)
                         const float* __restrict__ b1,  // (128)
                         const float* __restrict__ W2,  // (16, 128)
                         const float* __restrict__ b2,  // (16)
                         const float* __restrict__ ffB, // (179, 128)
                         const float* __restrict__ ffG,
                         const float* __restrict__ ffS,
                         const int*   __restrict__ ffP,
                         float* __restrict__ out)       // (2048, 16)
{
    __shared__ __align__(16) float sh_z[G][128];
    __shared__ __align__(16) float sh_x[G][32];
    __shared__ __align__(16) float sh_h1[G][128];
    __shared__ __align__(16) float sh_h2[G][128];
    __shared__ __align__(16) float sh_bd0[G][128];
    __shared__ __align__(16) float sh_bd1[G][128];
    __shared__ __align__(16) float sh_bd2[G][128];
    __shared__ __align__(16) float sh_stage[NWARP][2][128];  // double-buffered

    const int tid  = threadIdx.x;
    const int warp = tid >> 5;
    const int lane = tid & 31;
    const int base = blockIdx.x * G;

    for (int k = tid; k < G * 128; k += 256) {
        int g = k >> 7, i = k & 127;
        sh_z[g][i] = z[(base + g) * 128 + i];
    }
    for (int k = tid; k < G * 32; k += 256) {
        int g = k >> 5, i = k & 31;
        sh_x[g][i] = x[(base + g) * 32 + i];
    }
    __syncthreads();

    // ---------------- Phase A: W0 blocks (0..31) + bias blocks (32,161,178)
    for (int t = warp; t < 35; t += NWARP) {
        FF f;
        float u0, u1, u2, u3;
        if (t < 32) {
            ff_load(f, t, lane, ffB, ffG, ffS, ffP);
            // block t = W0 rows 4t..4t+3; element e=4l+q -> row = l>>3, i = 4*(l&7)+q
            const int row = lane >> 3;
            const int ic  = (lane & 7) << 2;
            float4 w4 = *reinterpret_cast<const float4*>(W0 + (4 * t + row) * 32 + ic);
#pragma unroll 1
            for (int g = 0; g < G; g++) {
                ff_apply(f, sh_z[g], sh_stage[warp][g & 1], lane, u0, u1, u2, u3);
                float4 x4 = *reinterpret_cast<const float4*>(sh_x[g] + ic);
                float acc = (w4.x + u0) * x4.x + (w4.y + u1) * x4.y
                          + (w4.z + u2) * x4.z + (w4.w + u3) * x4.w;
                acc += __shfl_xor_sync(FULLMASK, acc, 1);
                acc += __shfl_xor_sync(FULLMASK, acc, 2);
                acc += __shfl_xor_sync(FULLMASK, acc, 4);
                if ((lane & 7) == 0) sh_h1[g][4 * t + row] = acc;
            }
        } else {
            int r = (t == 32) ? 32 : (t == 33) ? 161 : 178;
            float (*bd)[128] = (t == 32) ? sh_bd0 : (t == 33) ? sh_bd1 : sh_bd2;
            ff_load(f, r, lane, ffB, ffG, ffS, ffP);
#pragma unroll 1
            for (int g = 0; g < G; g++) {
                ff_apply(f, sh_z[g], sh_stage[warp][g & 1], lane, u0, u1, u2, u3);
                reinterpret_cast<float4*>(bd[g])[lane] = make_float4(u0, u1, u2, u3);
            }
        }
    }
    __syncthreads();
    for (int k = tid; k < G * 128; k += 256) {
        int g = k >> 7, j = k & 127;
        sh_h1[g][j] = fmaxf(sh_h1[g][j] + b0[j] + sh_bd0[g][j], 0.0f);
    }
    __syncthreads();

    // ---------------- Phase B: W1 blocks (33..160); block 33+t = W1 row t
    for (int t = warp; t < 128; t += NWARP) {
        FF f;
        float u0, u1, u2, u3;
        ff_load(f, 33 + t, lane, ffB, ffG, ffS, ffP);
        float4 w4 = reinterpret_cast<const float4*>(W1 + t * 128)[lane];
#pragma unroll 1
        for (int g = 0; g < G; g++) {
            ff_apply(f, sh_z[g], sh_stage[warp][g & 1], lane, u0, u1, u2, u3);
            float4 h4 = reinterpret_cast<const float4*>(sh_h1[g])[lane];
            float acc = (w4.x + u0) * h4.x + (w4.y + u1) * h4.y
                      + (w4.z + u2) * h4.z + (w4.w + u3) * h4.w;
#pragma unroll
            for (int m = 16; m >= 1; m >>= 1) acc += __shfl_xor_sync(FULLMASK, acc, m);
            if (lane == 0) sh_h2[g][t] = acc;
        }
    }
    __syncthreads();
    for (int k = tid; k < G * 128; k += 256) {
        int g = k >> 7, j = k & 127;
        sh_h2[g][j] = fmaxf(sh_h2[g][j] + b1[j] + sh_bd1[g][j], 0.0f);
    }
    __syncthreads();

    // ---------------- Phase C: W2 blocks (162..177); block 162+t = W2 row t
    for (int t = warp; t < 16; t += NWARP) {
        FF f;
        float u0, u1, u2, u3;
        ff_load(f, 162 + t, lane, ffB, ffG, ffS, ffP);
        float4 w4 = reinterpret_cast<const float4*>(W2 + t * 128)[lane];
        float bias = b2[t];
#pragma unroll 1
        for (int g = 0; g < G; g++) {
            ff_apply(f, sh_z[g], sh_stage[warp][g & 1], lane, u0, u1, u2, u3);
            float4 h4 = reinterpret_cast<const float4*>(sh_h2[g])[lane];
            float acc = (w4.x + u0) * h4.x + (w4.y + u1) * h4.y
                      + (w4.z + u2) * h4.z + (w4.w + u3) * h4.w;
#pragma unroll
            for (int m = 16; m >= 1; m >>= 1) acc += __shfl_xor_sync(FULLMASK, acc, m);
            if (lane == 0) out[(base + g) * 16 + t] = acc + bias + sh_bd2[g][t];
        }
    }
}

extern "C" void kernel_launch(void* const* d_in, const int* in_sizes, int n_in,
                              void* d_out, int out_size) {
    (void)in_sizes; (void)n_in; (void)out_size;
    const float* x   = (const float*)d_in[0];
    const float* z   = (const float*)d_in[1];
    const float* W0  = (const float*)d_in[2];
    const float* b0  = (const float*)d_in[3];
    const float* W1  = (const float*)d_in[4];
    const float* b1  = (const float*)d_in[5];
    const float* W2  = (const float*)d_in[6];
    const float* b2  = (const float*)d_in[7];
    const float* ffB = (const float*)d_in[8];
    const float* ffG = (const float*)d_in[9];
    const float* ffS = (const float*)d_in[10];
    const int*   ffP = (const int*)d_in[11];
    float* out = (float*)d_out;

    mlp_fastfood_kernel<<<512, 256>>>(x, z, W0, b0, W1, b1, W2, b2,
                                      ffB, ffG, ffS, ffP, out);
}